// round 6
// baseline (speedup 1.0000x reference)
#include <cuda_runtime.h>
#include <math.h>

// ---------------- problem constants ----------------
#define CS 128           // encoder seq len
#define CB 64            // batch
#define CH 1024          // hidden = input = output width
#define CG 4096          // 4*H
#define CT 64            // decoder steps
#define BH (CB * CH)     // 65536

// ---------------- static device scratch (no runtime allocation) -------------
__device__ float g_xproj[(long)CS * CB * CG];   // 134 MB input projections
__device__ float g_seq0[(long)CS * CB * CH];    // 33 MB layer-0 encoder h sequence
__device__ float g_state[7 * BH];               // hzero | h[2][2] | c[2]

// ---------------- f32x2 helpers ----------------
__device__ __forceinline__ void ffma2(unsigned long long &acc,
                                      unsigned long long a2,
                                      unsigned long long b2) {
    asm("fma.rn.f32x2 %0, %1, %2, %0;" : "+l"(acc) : "l"(a2), "l"(b2));
}
__device__ __forceinline__ unsigned long long pkdup(float a) {
    unsigned long long r;
    asm("mov.b64 %0, {%1, %1};" : "=l"(r) : "f"(a));
    return r;
}
__device__ __forceinline__ unsigned long long pk2(float x, float y) {
    unsigned long long r;
    asm("mov.b64 %0, {%1, %2};" : "=l"(r) : "f"(x), "f"(y));
    return r;
}
__device__ __forceinline__ void unpk2(unsigned long long v, float &x, float &y) {
    asm("mov.b64 {%0, %1}, %2;" : "=f"(x), "=f"(y) : "l"(v));
}
__device__ __forceinline__ float sigf(float x) {
    return 1.0f / (1.0f + expf(-x));
}

// ---------------- zero fill ----------------
__global__ void kzero(float *a, int n) {
    int i = blockIdx.x * 256 + threadIdx.x;
    if (i < n) a[i] = 0.0f;
}

// ---------------- big GEMM: C[M,4096] = A[M,1024] @ W[4096,1024]^T + bias ---
// 128x128 tile, K-chunk 16, 256 threads, 8x8 per thread via f32x2.
__global__ __launch_bounds__(256, 1)
void kgemm_big(const float *__restrict__ A, const float *__restrict__ W,
               const float *__restrict__ bias, float *__restrict__ C) {
    const int K = 1024;
    const int N = 4096;
    __shared__ float sA[16][132];
    __shared__ float sB[16][132];
    const int tid = threadIdx.x;
    const int m0 = blockIdx.y * 128;
    const int n0 = blockIdx.x * 128;
    const int r0 = tid >> 2;       // 0..63
    const int kq = (tid & 3) * 4;  // 0,4,8,12
    const float *Ap0 = A + (long)(m0 + r0) * K + kq;
    const float *Ap1 = Ap0 + 64L * K;
    const float *Wp0 = W + (long)(n0 + r0) * K + kq;
    const float *Wp1 = Wp0 + 64L * K;
    const int ty = tid >> 4;   // 0..15 -> rows ty*8..+7
    const int tx = tid & 15;   // 0..15 -> cols tx*8..+7

    unsigned long long acc[8][4];
#pragma unroll
    for (int i = 0; i < 8; i++)
#pragma unroll
        for (int j = 0; j < 4; j++) acc[i][j] = 0ULL;

    for (int k0 = 0; k0 < K; k0 += 16) {
        float4 ra0 = *(const float4 *)(Ap0 + k0);
        float4 ra1 = *(const float4 *)(Ap1 + k0);
        float4 rw0 = *(const float4 *)(Wp0 + k0);
        float4 rw1 = *(const float4 *)(Wp1 + k0);
        __syncthreads();
        sA[kq + 0][r0] = ra0.x; sA[kq + 1][r0] = ra0.y;
        sA[kq + 2][r0] = ra0.z; sA[kq + 3][r0] = ra0.w;
        sA[kq + 0][r0 + 64] = ra1.x; sA[kq + 1][r0 + 64] = ra1.y;
        sA[kq + 2][r0 + 64] = ra1.z; sA[kq + 3][r0 + 64] = ra1.w;
        sB[kq + 0][r0] = rw0.x; sB[kq + 1][r0] = rw0.y;
        sB[kq + 2][r0] = rw0.z; sB[kq + 3][r0] = rw0.w;
        sB[kq + 0][r0 + 64] = rw1.x; sB[kq + 1][r0 + 64] = rw1.y;
        sB[kq + 2][r0 + 64] = rw1.z; sB[kq + 3][r0 + 64] = rw1.w;
        __syncthreads();
#pragma unroll
        for (int kk = 0; kk < 16; kk++) {
            const float4 av0 = *(const float4 *)&sA[kk][ty * 8];
            const float4 av1 = *(const float4 *)&sA[kk][ty * 8 + 4];
            const float4 bv0 = *(const float4 *)&sB[kk][tx * 8];
            const float4 bv1 = *(const float4 *)&sB[kk][tx * 8 + 4];
            unsigned long long b2[4];
            b2[0] = pk2(bv0.x, bv0.y);
            b2[1] = pk2(bv0.z, bv0.w);
            b2[2] = pk2(bv1.x, bv1.y);
            b2[3] = pk2(bv1.z, bv1.w);
            const float af[8] = {av0.x, av0.y, av0.z, av0.w,
                                 av1.x, av1.y, av1.z, av1.w};
#pragma unroll
            for (int i = 0; i < 8; i++) {
                unsigned long long ap = pkdup(af[i]);
                ffma2(acc[i][0], ap, b2[0]);
                ffma2(acc[i][1], ap, b2[1]);
                ffma2(acc[i][2], ap, b2[2]);
                ffma2(acc[i][3], ap, b2[3]);
            }
        }
    }
    const float4 bs0 = *(const float4 *)&bias[n0 + tx * 8];
    const float4 bs1 = *(const float4 *)&bias[n0 + tx * 8 + 4];
#pragma unroll
    for (int i = 0; i < 8; i++) {
        float v[8];
        unpk2(acc[i][0], v[0], v[1]);
        unpk2(acc[i][1], v[2], v[3]);
        unpk2(acc[i][2], v[4], v[5]);
        unpk2(acc[i][3], v[6], v[7]);
        float *Crow = C + (long)(m0 + ty * 8 + i) * N + n0 + tx * 8;
        float4 o0 = make_float4(v[0] + bs0.x, v[1] + bs0.y, v[2] + bs0.z, v[3] + bs0.w);
        float4 o1 = make_float4(v[4] + bs1.x, v[5] + bs1.y, v[6] + bs1.z, v[7] + bs1.w);
        *(float4 *)Crow = o0;
        *(float4 *)(Crow + 4) = o1;
    }
}

// ---------------- fused LSTM step -------------------------------------------
// gates[b, g*H+j] = (x @ wih^T, if x) + h_in @ whh^T + (pre | bias)
// then c/h update for the block's 8 j-columns. Grid = 128 blocks, 256 threads.
__global__ __launch_bounds__(256, 1)
void kstep(const float *__restrict__ x, int xstride,
           const float *__restrict__ wih,
           const float *__restrict__ h_in,
           const float *__restrict__ whh,
           const float *__restrict__ pre,    // [B][4096] incl. bias, or null
           const float *__restrict__ bias,   // [4096], used when pre == null
           float *__restrict__ h_out,
           float *__restrict__ c) {
    __shared__ float sA[16][68];
    __shared__ float sW[16][33];
    __shared__ float sG[32][65];
    const int tid = threadIdx.x;
    const int j0 = blockIdx.x * 8;
    const int tb = tid >> 5;   // 0..7 -> batch rows tb*8..+7
    const int tn = tid & 31;   // gate-col within tile: gate = tn>>3, jj = tn&7
    float acc[8];
#pragma unroll
    for (int i = 0; i < 8; i++) acc[i] = 0.0f;

    const int lb = tid >> 2;          // 0..63
    const int lk = (tid & 3) * 4;     // 0,4,8,12
    const int wn = (tid & 127) >> 2;  // 0..31
    const int wk = (tid & 3) * 4;
    const bool wload = (tid < 128);
    const int wrow = (wn >> 3) * CH + j0 + (wn & 7);

    for (int phase = 0; phase < 2; phase++) {
        const float *A;
        const float *W;
        int As;
        if (phase == 0) {
            if (x == nullptr) continue;
            A = x; As = xstride; W = wih;
        } else {
            A = h_in; As = CH; W = whh;
        }
        for (int k0 = 0; k0 < 1024; k0 += 16) {
            float4 av = *(const float4 *)(A + (long)lb * As + k0 + lk);
            float4 wv = make_float4(0.f, 0.f, 0.f, 0.f);
            if (wload) wv = *(const float4 *)(W + (long)wrow * 1024 + k0 + wk);
            __syncthreads();
            sA[lk + 0][lb] = av.x; sA[lk + 1][lb] = av.y;
            sA[lk + 2][lb] = av.z; sA[lk + 3][lb] = av.w;
            if (wload) {
                sW[wk + 0][wn] = wv.x; sW[wk + 1][wn] = wv.y;
                sW[wk + 2][wn] = wv.z; sW[wk + 3][wn] = wv.w;
            }
            __syncthreads();
#pragma unroll
            for (int kk = 0; kk < 16; kk++) {
                const float4 a0 = *(const float4 *)&sA[kk][tb * 8];
                const float4 a1 = *(const float4 *)&sA[kk][tb * 8 + 4];
                const float w = sW[kk][tn];
                acc[0] += a0.x * w; acc[1] += a0.y * w;
                acc[2] += a0.z * w; acc[3] += a0.w * w;
                acc[4] += a1.x * w; acc[5] += a1.y * w;
                acc[6] += a1.z * w; acc[7] += a1.w * w;
            }
        }
    }

    const int col = (tn >> 3) * CH + j0 + (tn & 7);
    if (pre != nullptr) {
#pragma unroll
        for (int i = 0; i < 8; i++)
            sG[tn][tb * 8 + i] = acc[i] + pre[(long)(tb * 8 + i) * CG + col];
    } else {
        const float bv = bias[col];
#pragma unroll
        for (int i = 0; i < 8; i++)
            sG[tn][tb * 8 + i] = acc[i] + bv;
    }
    __syncthreads();
    for (int e = tid; e < 512; e += 256) {
        const int b = e & 63;
        const int jj = e >> 6;
        const float gi = sG[jj][b];
        const float gf = sG[8 + jj][b];
        const float gg = sG[16 + jj][b];
        const float go = sG[24 + jj][b];
        const int idx = b * CH + j0 + jj;
        const float cv = c[idx];
        const float cn = sigf(gf) * cv + sigf(gi) * tanhf(gg);
        c[idx] = cn;
        h_out[idx] = sigf(go) * tanhf(cn);
    }
}

// ---------------- linear head: y[b][n0+tn] = h[b]·W[n]+b ---------------------
// Grid = 32 blocks (N=1024 / 32-col tiles), 256 threads, 8 rows x 1 col each.
__global__ __launch_bounds__(256, 1)
void klin(const float *__restrict__ h, const float *__restrict__ W,
          const float *__restrict__ bias, float *__restrict__ y, int ystride) {
    __shared__ float sA[16][68];
    __shared__ float sW[16][33];
    const int tid = threadIdx.x;
    const int n0 = blockIdx.x * 32;
    const int tb = tid >> 5;
    const int tn = tid & 31;
    float acc[8];
#pragma unroll
    for (int i = 0; i < 8; i++) acc[i] = 0.0f;
    const int lb = tid >> 2;
    const int lk = (tid & 3) * 4;
    const int wn = (tid & 127) >> 2;
    const int wk = (tid & 3) * 4;
    const bool wload = (tid < 128);
    for (int k0 = 0; k0 < 1024; k0 += 16) {
        float4 av = *(const float4 *)(h + (long)lb * 1024 + k0 + lk);
        float4 wv = make_float4(0.f, 0.f, 0.f, 0.f);
        if (wload) wv = *(const float4 *)(W + (long)(n0 + wn) * 1024 + k0 + wk);
        __syncthreads();
        sA[lk + 0][lb] = av.x; sA[lk + 1][lb] = av.y;
        sA[lk + 2][lb] = av.z; sA[lk + 3][lb] = av.w;
        if (wload) {
            sW[wk + 0][wn] = wv.x; sW[wk + 1][wn] = wv.y;
            sW[wk + 2][wn] = wv.z; sW[wk + 3][wn] = wv.w;
        }
        __syncthreads();
#pragma unroll
        for (int kk = 0; kk < 16; kk++) {
            const float4 a0 = *(const float4 *)&sA[kk][tb * 8];
            const float4 a1 = *(const float4 *)&sA[kk][tb * 8 + 4];
            const float w = sW[kk][tn];
            acc[0] += a0.x * w; acc[1] += a0.y * w;
            acc[2] += a0.z * w; acc[3] += a0.w * w;
            acc[4] += a1.x * w; acc[5] += a1.y * w;
            acc[6] += a1.z * w; acc[7] += a1.w * w;
        }
    }
    const float bv = bias[n0 + tn];
#pragma unroll
    for (int i = 0; i < 8; i++)
        y[(long)(tb * 8 + i) * ystride + n0 + tn] = acc[i] + bv;
}

// ---------------- host orchestration ----------------------------------------
extern "C" void kernel_launch(void* const* d_in, const int* in_sizes, int n_in,
                              void* d_out, int out_size) {
    const float *input_seq = (const float *)d_in[0];   // [128,64,1024]
    const float *enc_wih   = (const float *)d_in[1];   // [2,4096,1024]
    const float *enc_whh   = (const float *)d_in[2];   // [2,4096,1024]
    const float *enc_b     = (const float *)d_in[3];   // [2,4096]
    const float *dec_wih   = (const float *)d_in[4];
    const float *dec_whh   = (const float *)d_in[5];
    const float *dec_b     = (const float *)d_in[6];
    const float *lin_w     = (const float *)d_in[7];   // [1024,1024]
    const float *lin_b     = (const float *)d_in[8];   // [1024]
    float *out = (float *)d_out;                       // [64,64,1024]

    float *xproj = nullptr, *seq0 = nullptr, *state = nullptr;
    cudaGetSymbolAddress((void **)&xproj, g_xproj);
    cudaGetSymbolAddress((void **)&seq0, g_seq0);
    cudaGetSymbolAddress((void **)&state, g_state);

    float *hzero = state;                              // [BH] zeros
    // h buffers: state + (1 + l*2 + p)*BH ; c buffers: state + (5+l)*BH
    float *c0 = state + 5 * BH;
    float *c1 = state + 6 * BH;
#define HB(l, p) (state + (1 + (l) * 2 + (p)) * BH)

    // zero hzero, all h parities, c0, c1 (idempotent each launch)
    kzero<<<(7 * BH + 255) / 256, 256>>>(state, 7 * BH);

    // ---- encoder layer 0 ----
    kgemm_big<<<dim3(32, 64), 256>>>(input_seq, enc_wih, enc_b, xproj);
    for (int s = 0; s < CS; s++) {
        kstep<<<128, 256>>>(nullptr, 0, nullptr,
                            (s == 0) ? hzero : (seq0 + (long)(s - 1) * BH),
                            enc_whh,
                            xproj + (long)s * CB * CG, nullptr,
                            seq0 + (long)s * BH, c0);
    }
    // ---- encoder layer 1 ----
    kgemm_big<<<dim3(32, 64), 256>>>(seq0, enc_wih + (long)CG * CH,
                                     enc_b + CG, xproj);
    for (int s = 0; s < CS; s++) {
        kstep<<<128, 256>>>(nullptr, 0, nullptr,
                            HB(1, s & 1),
                            enc_whh + (long)CG * CH,
                            xproj + (long)s * CB * CG, nullptr,
                            HB(1, (s & 1) ^ 1), c1);
    }

    // ---- autoregressive decoder ----
    for (int t = 0; t < CT; t++) {
        const float *x0 = (t == 0) ? (input_seq + 127L * CB * CH)
                                   : (out + (long)(t - 1) * CH);
        const int xs = (t == 0) ? CH : (CT * CH);
        const float *h0in = (t == 0) ? (seq0 + 127L * BH) : HB(0, t & 1);
        // layer 0: x = previous output (or last encoder input)
        kstep<<<128, 256>>>(x0, xs, dec_wih,
                            h0in, dec_whh,
                            nullptr, dec_b,
                            HB(0, (t & 1) ^ 1), c0);
        // layer 1: x = layer-0 h just computed
        kstep<<<128, 256>>>(HB(0, (t & 1) ^ 1), CH, dec_wih + (long)CG * CH,
                            HB(1, t & 1), dec_whh + (long)CG * CH,
                            nullptr, dec_b + CG,
                            HB(1, (t & 1) ^ 1), c1);
        // linear head -> out[:, t, :]
        klin<<<32, 256>>>(HB(1, (t & 1) ^ 1), lin_w, lin_b,
                          out + (long)t * CH, CT * CH);
    }
#undef HB
}

// round 8
// speedup vs baseline: 1.0310x; 1.0310x over previous
#include <cuda_runtime.h>
#include <math.h>

// ---------------- problem constants ----------------
#define CS 128           // encoder seq len
#define CB 64            // batch
#define CH 1024          // hidden = input = output width
#define CG 4096          // 4*H
#define CT 64            // decoder steps
#define BH (CB * CH)     // 65536

// ---------------- static device scratch (no runtime allocation) -------------
__device__ float g_xproj[(long)CS * CB * CG];   // 134 MB input projections
__device__ float g_seq0[(long)CS * CB * CH];    // 33 MB layer-0 encoder h sequence
__device__ float g_state[7 * BH];               // hzero | h[2][2] | c[2]

// ---------------- f32x2 helpers ----------------
__device__ __forceinline__ void ffma2(unsigned long long &acc,
                                      unsigned long long a2,
                                      unsigned long long b2) {
    asm("fma.rn.f32x2 %0, %1, %2, %0;" : "+l"(acc) : "l"(a2), "l"(b2));
}
__device__ __forceinline__ unsigned long long pkdup(float a) {
    unsigned long long r;
    asm("mov.b64 %0, {%1, %1};" : "=l"(r) : "f"(a));
    return r;
}
__device__ __forceinline__ unsigned long long pk2(float x, float y) {
    unsigned long long r;
    asm("mov.b64 %0, {%1, %2};" : "=l"(r) : "f"(x), "f"(y));
    return r;
}
__device__ __forceinline__ void unpk2(unsigned long long v, float &x, float &y) {
    asm("mov.b64 {%0, %1}, %2;" : "=f"(x), "=f"(y) : "l"(v));
}
__device__ __forceinline__ float sigf(float x) {
    return 1.0f / (1.0f + expf(-x));
}

// ---------------- zero fill ----------------
__global__ void kzero(float *a, int n) {
    int i = blockIdx.x * 256 + threadIdx.x;
    if (i < n) a[i] = 0.0f;
}

// ---------------- big GEMM: C[M,4096] = A[M,1024] @ W[4096,1024]^T + bias ---
// 128x128 tile, K-chunk 16, 256 threads, 8x8 per thread via f32x2.
__global__ __launch_bounds__(256, 1)
void kgemm_big(const float *__restrict__ A, const float *__restrict__ W,
               const float *__restrict__ bias, float *__restrict__ C) {
    const int K = 1024;
    const int N = 4096;
    __shared__ float sA[16][132];
    __shared__ float sB[16][132];
    const int tid = threadIdx.x;
    const int m0 = blockIdx.y * 128;
    const int n0 = blockIdx.x * 128;
    const int r0 = tid >> 2;       // 0..63
    const int kq = (tid & 3) * 4;  // 0,4,8,12
    const float *Ap0 = A + (long)(m0 + r0) * K + kq;
    const float *Ap1 = Ap0 + 64L * K;
    const float *Wp0 = W + (long)(n0 + r0) * K + kq;
    const float *Wp1 = Wp0 + 64L * K;
    const int ty = tid >> 4;   // 0..15 -> rows ty*8..+7
    const int tx = tid & 15;   // 0..15 -> cols tx*8..+7

    unsigned long long acc[8][4];
#pragma unroll
    for (int i = 0; i < 8; i++)
#pragma unroll
        for (int j = 0; j < 4; j++) acc[i][j] = 0ULL;

    for (int k0 = 0; k0 < K; k0 += 16) {
        float4 ra0 = *(const float4 *)(Ap0 + k0);
        float4 ra1 = *(const float4 *)(Ap1 + k0);
        float4 rw0 = *(const float4 *)(Wp0 + k0);
        float4 rw1 = *(const float4 *)(Wp1 + k0);
        __syncthreads();
        sA[kq + 0][r0] = ra0.x; sA[kq + 1][r0] = ra0.y;
        sA[kq + 2][r0] = ra0.z; sA[kq + 3][r0] = ra0.w;
        sA[kq + 0][r0 + 64] = ra1.x; sA[kq + 1][r0 + 64] = ra1.y;
        sA[kq + 2][r0 + 64] = ra1.z; sA[kq + 3][r0 + 64] = ra1.w;
        sB[kq + 0][r0] = rw0.x; sB[kq + 1][r0] = rw0.y;
        sB[kq + 2][r0] = rw0.z; sB[kq + 3][r0] = rw0.w;
        sB[kq + 0][r0 + 64] = rw1.x; sB[kq + 1][r0 + 64] = rw1.y;
        sB[kq + 2][r0 + 64] = rw1.z; sB[kq + 3][r0 + 64] = rw1.w;
        __syncthreads();
#pragma unroll
        for (int kk = 0; kk < 16; kk++) {
            const float4 av0 = *(const float4 *)&sA[kk][ty * 8];
            const float4 av1 = *(const float4 *)&sA[kk][ty * 8 + 4];
            const float4 bv0 = *(const float4 *)&sB[kk][tx * 8];
            const float4 bv1 = *(const float4 *)&sB[kk][tx * 8 + 4];
            unsigned long long b2[4];
            b2[0] = pk2(bv0.x, bv0.y);
            b2[1] = pk2(bv0.z, bv0.w);
            b2[2] = pk2(bv1.x, bv1.y);
            b2[3] = pk2(bv1.z, bv1.w);
            const float af[8] = {av0.x, av0.y, av0.z, av0.w,
                                 av1.x, av1.y, av1.z, av1.w};
#pragma unroll
            for (int i = 0; i < 8; i++) {
                unsigned long long ap = pkdup(af[i]);
                ffma2(acc[i][0], ap, b2[0]);
                ffma2(acc[i][1], ap, b2[1]);
                ffma2(acc[i][2], ap, b2[2]);
                ffma2(acc[i][3], ap, b2[3]);
            }
        }
    }
    const float4 bs0 = *(const float4 *)&bias[n0 + tx * 8];
    const float4 bs1 = *(const float4 *)&bias[n0 + tx * 8 + 4];
#pragma unroll
    for (int i = 0; i < 8; i++) {
        float v[8];
        unpk2(acc[i][0], v[0], v[1]);
        unpk2(acc[i][1], v[2], v[3]);
        unpk2(acc[i][2], v[4], v[5]);
        unpk2(acc[i][3], v[6], v[7]);
        float *Crow = C + (long)(m0 + ty * 8 + i) * N + n0 + tx * 8;
        float4 o0 = make_float4(v[0] + bs0.x, v[1] + bs0.y, v[2] + bs0.z, v[3] + bs0.w);
        float4 o1 = make_float4(v[4] + bs1.x, v[5] + bs1.y, v[6] + bs1.z, v[7] + bs1.w);
        *(float4 *)Crow = o0;
        *(float4 *)(Crow + 4) = o1;
    }
}

// ---------------- fused LSTM step -------------------------------------------
// gates[b, g*H+j] = (x @ wih^T, if x) + h_in @ whh^T + (pre | bias)
// then c/h update for the block's 8 j-columns. Grid = 128 blocks, 256 threads.
__global__ __launch_bounds__(256, 1)
void kstep(const float *__restrict__ x, int xstride,
           const float *__restrict__ wih,
           const float *__restrict__ h_in,
           const float *__restrict__ whh,
           const float *__restrict__ pre,    // [B][4096] incl. bias, or null
           const float *__restrict__ bias,   // [4096], used when pre == null
           float *__restrict__ h_out,
           float *__restrict__ c) {
    __shared__ float sA[16][68];
    __shared__ float sW[16][33];
    __shared__ float sG[32][65];
    const int tid = threadIdx.x;
    const int j0 = blockIdx.x * 8;
    const int tb = tid >> 5;   // 0..7 -> batch rows tb*8..+7
    const int tn = tid & 31;   // gate-col within tile: gate = tn>>3, jj = tn&7
    float acc[8];
#pragma unroll
    for (int i = 0; i < 8; i++) acc[i] = 0.0f;

    const int lb = tid >> 2;          // 0..63
    const int lk = (tid & 3) * 4;     // 0,4,8,12
    const int wn = (tid & 127) >> 2;  // 0..31
    const int wk = (tid & 3) * 4;
    const bool wload = (tid < 128);
    const int wrow = (wn >> 3) * CH + j0 + (wn & 7);

    for (int phase = 0; phase < 2; phase++) {
        const float *A;
        const float *W;
        int As;
        if (phase == 0) {
            if (x == nullptr) continue;
            A = x; As = xstride; W = wih;
        } else {
            A = h_in; As = CH; W = whh;
        }
        for (int k0 = 0; k0 < 1024; k0 += 16) {
            float4 av = *(const float4 *)(A + (long)lb * As + k0 + lk);
            float4 wv = make_float4(0.f, 0.f, 0.f, 0.f);
            if (wload) wv = *(const float4 *)(W + (long)wrow * 1024 + k0 + wk);
            __syncthreads();
            sA[lk + 0][lb] = av.x; sA[lk + 1][lb] = av.y;
            sA[lk + 2][lb] = av.z; sA[lk + 3][lb] = av.w;
            if (wload) {
                sW[wk + 0][wn] = wv.x; sW[wk + 1][wn] = wv.y;
                sW[wk + 2][wn] = wv.z; sW[wk + 3][wn] = wv.w;
            }
            __syncthreads();
#pragma unroll
            for (int kk = 0; kk < 16; kk++) {
                const float4 a0 = *(const float4 *)&sA[kk][tb * 8];
                const float4 a1 = *(const float4 *)&sA[kk][tb * 8 + 4];
                const float w = sW[kk][tn];
                acc[0] += a0.x * w; acc[1] += a0.y * w;
                acc[2] += a0.z * w; acc[3] += a0.w * w;
                acc[4] += a1.x * w; acc[5] += a1.y * w;
                acc[6] += a1.z * w; acc[7] += a1.w * w;
            }
        }
    }

    const int col = (tn >> 3) * CH + j0 + (tn & 7);
    if (pre != nullptr) {
#pragma unroll
        for (int i = 0; i < 8; i++)
            sG[tn][tb * 8 + i] = acc[i] + pre[(long)(tb * 8 + i) * CG + col];
    } else {
        const float bv = bias[col];
#pragma unroll
        for (int i = 0; i < 8; i++)
            sG[tn][tb * 8 + i] = acc[i] + bv;
    }
    __syncthreads();
    for (int e = tid; e < 512; e += 256) {
        const int b = e & 63;
        const int jj = e >> 6;
        const float gi = sG[jj][b];
        const float gf = sG[8 + jj][b];
        const float gg = sG[16 + jj][b];
        const float go = sG[24 + jj][b];
        const int idx = b * CH + j0 + jj;
        const float cv = c[idx];
        const float cn = sigf(gf) * cv + sigf(gi) * tanhf(gg);
        c[idx] = cn;
        h_out[idx] = sigf(go) * tanhf(cn);
    }
}

// ---------------- linear head: y[b][n0+tn] = h[b]·W[n]+b ---------------------
// Grid = 32 blocks (N=1024 / 32-col tiles), 256 threads, 8 rows x 1 col each.
__global__ __launch_bounds__(256, 1)
void klin(const float *__restrict__ h, const float *__restrict__ W,
          const float *__restrict__ bias, float *__restrict__ y, int ystride) {
    __shared__ float sA[16][68];
    __shared__ float sW[16][33];
    const int tid = threadIdx.x;
    const int n0 = blockIdx.x * 32;
    const int tb = tid >> 5;
    const int tn = tid & 31;
    float acc[8];
#pragma unroll
    for (int i = 0; i < 8; i++) acc[i] = 0.0f;
    const int lb = tid >> 2;
    const int lk = (tid & 3) * 4;
    const int wn = (tid & 127) >> 2;
    const int wk = (tid & 3) * 4;
    const bool wload = (tid < 128);
    for (int k0 = 0; k0 < 1024; k0 += 16) {
        float4 av = *(const float4 *)(h + (long)lb * 1024 + k0 + lk);
        float4 wv = make_float4(0.f, 0.f, 0.f, 0.f);
        if (wload) wv = *(const float4 *)(W + (long)(n0 + wn) * 1024 + k0 + wk);
        __syncthreads();
        sA[lk + 0][lb] = av.x; sA[lk + 1][lb] = av.y;
        sA[lk + 2][lb] = av.z; sA[lk + 3][lb] = av.w;
        if (wload) {
            sW[wk + 0][wn] = wv.x; sW[wk + 1][wn] = wv.y;
            sW[wk + 2][wn] = wv.z; sW[wk + 3][wn] = wv.w;
        }
        __syncthreads();
#pragma unroll
        for (int kk = 0; kk < 16; kk++) {
            const float4 a0 = *(const float4 *)&sA[kk][tb * 8];
            const float4 a1 = *(const float4 *)&sA[kk][tb * 8 + 4];
            const float w = sW[kk][tn];
            acc[0] += a0.x * w; acc[1] += a0.y * w;
            acc[2] += a0.z * w; acc[3] += a0.w * w;
            acc[4] += a1.x * w; acc[5] += a1.y * w;
            acc[6] += a1.z * w; acc[7] += a1.w * w;
        }
    }
    const float bv = bias[n0 + tn];
#pragma unroll
    for (int i = 0; i < 8; i++)
        y[(long)(tb * 8 + i) * ystride + n0 + tn] = acc[i] + bv;
}

// ---------------- host orchestration ----------------------------------------
extern "C" void kernel_launch(void* const* d_in, const int* in_sizes, int n_in,
                              void* d_out, int out_size) {
    const float *input_seq = (const float *)d_in[0];   // [128,64,1024]
    const float *enc_wih   = (const float *)d_in[1];   // [2,4096,1024]
    const float *enc_whh   = (const float *)d_in[2];   // [2,4096,1024]
    const float *enc_b     = (const float *)d_in[3];   // [2,4096]
    const float *dec_wih   = (const float *)d_in[4];
    const float *dec_whh   = (const float *)d_in[5];
    const float *dec_b     = (const float *)d_in[6];
    const float *lin_w     = (const float *)d_in[7];   // [1024,1024]
    const float *lin_b     = (const float *)d_in[8];   // [1024]
    float *out = (float *)d_out;                       // [64,64,1024]

    float *xproj = nullptr, *seq0 = nullptr, *state = nullptr;
    cudaGetSymbolAddress((void **)&xproj, g_xproj);
    cudaGetSymbolAddress((void **)&seq0, g_seq0);
    cudaGetSymbolAddress((void **)&state, g_state);

    float *hzero = state;                              // [BH] zeros
    // h buffers: state + (1 + l*2 + p)*BH ; c buffers: state + (5+l)*BH
    float *c0 = state + 5 * BH;
    float *c1 = state + 6 * BH;
#define HB(l, p) (state + (1 + (l) * 2 + (p)) * BH)

    // zero hzero, all h parities, c0, c1 (idempotent each launch)
    kzero<<<(7 * BH + 255) / 256, 256>>>(state, 7 * BH);

    // ---- encoder layer 0 ----
    kgemm_big<<<dim3(32, 64), 256>>>(input_seq, enc_wih, enc_b, xproj);
    for (int s = 0; s < CS; s++) {
        kstep<<<128, 256>>>(nullptr, 0, nullptr,
                            (s == 0) ? hzero : (seq0 + (long)(s - 1) * BH),
                            enc_whh,
                            xproj + (long)s * CB * CG, nullptr,
                            seq0 + (long)s * BH, c0);
    }
    // ---- encoder layer 1 ----
    kgemm_big<<<dim3(32, 64), 256>>>(seq0, enc_wih + (long)CG * CH,
                                     enc_b + CG, xproj);
    for (int s = 0; s < CS; s++) {
        kstep<<<128, 256>>>(nullptr, 0, nullptr,
                            HB(1, s & 1),
                            enc_whh + (long)CG * CH,
                            xproj + (long)s * CB * CG, nullptr,
                            HB(1, (s & 1) ^ 1), c1);
    }

    // ---- autoregressive decoder ----
    for (int t = 0; t < CT; t++) {
        const float *x0 = (t == 0) ? (input_seq + 127L * CB * CH)
                                   : (out + (long)(t - 1) * CH);
        const int xs = (t == 0) ? CH : (CT * CH);
        const float *h0in = (t == 0) ? (seq0 + 127L * BH) : HB(0, t & 1);
        // layer 0: x = previous output (or last encoder input)
        kstep<<<128, 256>>>(x0, xs, dec_wih,
                            h0in, dec_whh,
                            nullptr, dec_b,
                            HB(0, (t & 1) ^ 1), c0);
        // layer 1: x = layer-0 h just computed
        kstep<<<128, 256>>>(HB(0, (t & 1) ^ 1), CH, dec_wih + (long)CG * CH,
                            HB(1, t & 1), dec_whh + (long)CG * CH,
                            nullptr, dec_b + CG,
                            HB(1, (t & 1) ^ 1), c1);
        // linear head -> out[:, t, :]
        klin<<<32, 256>>>(HB(1, (t & 1) ^ 1), lin_w, lin_b,
                          out + (long)t * CH, CT * CH);
    }
#undef HB
}